// round 12
// baseline (speedup 1.0000x reference)
#include <cuda_runtime.h>
#include <cuda_bf16.h>
#include <math_constants.h>
#include <cstdint>

// VectorQuantizer: B=32, D=64, H=W=32, K=1024
// Output layout (f32 concat): [loss(1)][quantized BxDxHxW (2097152)][indices BxHW (32768)]
//
// bf16 warp-MMA prefilter (provable error bound) + exact fp32 rescore of the
// tiny candidate set + deterministic packed-u64 atomicMin argmin merge.

#define ND 64
#define NHW 1024
#define NK 1024
#define NPTS 32768

__device__ float              g_e2[NK];
__device__ float              g_se[NK];          // sqrt(e2)
__device__ __nv_bfloat16      g_ebf[NK * ND];    // codebook bf16
__device__ unsigned           g_emaxr;           // max sqrt(e2) bits (zero-init)
__device__ float              g_smin[NPTS];      // approx min s per point
__device__ unsigned long long g_best[NPTS];      // (dist_bits<<32)|code
__device__ double             g_partials[128];

// dynamic smem offsets (bytes)
#define SM_ABF 0                 // A bf16: 128 rows x 36 words (144B) = 18432
#define SM_B   18432             // B ping-pong: 2 x (32 rows x 36 words) = 9216
#define SM_X2  27648             // 128 floats
#define SM_AFP 28160             // A fp32: 128 x 64 floats = 32768 (pass B only)
#define DYN_A  28160
#define DYN_B  60928

// ---------------------------------------------------------------------------
// Prep: e2 (proven R10 order), sqrt(e2), global max, bf16 codebook
// ---------------------------------------------------------------------------
__global__ void vq_prep_kernel(const float* __restrict__ emb) {
    int tid = blockIdx.x * 256 + threadIdx.x;   // 8192 threads
    int k   = tid >> 3;
    int sub = tid & 7;
    const float* r = emb + k * ND + sub * 8;
    float v[8];
    float s = 0.f;
#pragma unroll
    for (int d = 0; d < 8; d++) { v[d] = r[d]; s = __fmaf_rn(v[d], v[d], s); }
    s += __shfl_down_sync(0xffffffffu, s, 4, 8);
    s += __shfl_down_sync(0xffffffffu, s, 2, 8);
    s += __shfl_down_sync(0xffffffffu, s, 1, 8);
    if (sub == 0) {
        g_e2[k] = s;
        float sr = sqrtf(s);
        g_se[k] = sr;
        atomicMax(&g_emaxr, __float_as_uint(sr));   // positive -> bits monotone
    }
#pragma unroll
    for (int d = 0; d < 8; d++)
        g_ebf[k * ND + sub * 8 + d] = __float2bfloat16(v[d]);
}

// ---------------------------------------------------------------------------
__device__ __forceinline__ void mma_bf16(float* acc, const uint32_t* a,
                                         uint32_t b0, uint32_t b1) {
    asm volatile(
        "mma.sync.aligned.m16n8k16.row.col.f32.bf16.bf16.f32 "
        "{%0,%1,%2,%3}, {%4,%5,%6,%7}, {%8,%9}, {%0,%1,%2,%3};"
        : "+f"(acc[0]), "+f"(acc[1]), "+f"(acc[2]), "+f"(acc[3])
        : "r"(a[0]), "r"(a[1]), "r"(a[2]), "r"(a[3]), "r"(b0), "r"(b1));
}

// exact fp32 rescore: dist = fl(fl(x2 - 2*dot) + e2), sequential ascending dot
__device__ __forceinline__ void rescore(const float* __restrict__ xr, float x2,
                                        int code, const float* __restrict__ emb,
                                        unsigned long long* dst) {
    const float* er = emb + (size_t)code * ND;
    float dot = 0.f;
#pragma unroll
    for (int d = 0; d < ND; d++) dot = __fmaf_rn(xr[d], __ldg(er + d), dot);
    float dist = __fadd_rn(__fmaf_rn(-2.0f, dot, x2), __ldg(&g_e2[code]));
    unsigned long long pk =
        ((unsigned long long)__float_as_uint(dist) << 32) | (unsigned)code;
    atomicMin(dst, pk);
}

// ---------------------------------------------------------------------------
// GEMM pass. 256 CTAs x 256 threads; CTA = 128 points, warp = m16, N = 1024
// codes in 32 chunks of 32, K = 64 (4 k16 steps). A resident in regs.
// RESCORE=0: track per-point approx min s, write g_smin, init g_best.
// RESCORE=1: threshold against g_smin and exact-rescore candidates.
// ---------------------------------------------------------------------------
template <int RESCORE>
__global__ void __launch_bounds__(256) vq_gemm_kernel(
    const float* __restrict__ x_in,
    const float* __restrict__ emb)
{
    extern __shared__ char smem[];
    uint32_t* abf = (uint32_t*)(smem + SM_ABF);      // stride 36 words/row
    uint32_t* bbf = (uint32_t*)(smem + SM_B);        // 2 bufs x 1152 words
    float*    sx2 = (float*)(smem + SM_X2);
    float*    afp = (float*)(smem + SM_AFP);

    const int t    = threadIdx.x;
    const int base = blockIdx.x * 128;

    // ---- stage A (threads 0..127: one point each, sequential-ascending x2) ----
    if (t < 128) {
        const int n  = base + t;
        const int b  = n >> 10;
        const int hw = n & 1023;
        const float* xp = x_in + (size_t)b * (ND * NHW) + hw;
        float x2 = 0.f;
        __nv_bfloat16* arow = (__nv_bfloat16*)(abf + t * 36);
#pragma unroll
        for (int d = 0; d < ND; d++) {
            float v = __ldg(xp + d * NHW);           // coalesced across threads
            x2 = __fmaf_rn(v, v, x2);                // bit-identical to ref regime
            arow[d] = __float2bfloat16(v);
            if (RESCORE) afp[t * ND + d] = v;
        }
        sx2[t] = x2;
        if (!RESCORE) g_best[n] = 0xFFFFFFFFFFFFFFFFull;   // init for pass B
    } else {
        // threads 128..255: stage B chunk 0 (codes 0..31)
        const uint32_t* src = (const uint32_t*)g_ebf;
        int tt = t - 128;
#pragma unroll
        for (int i = 0; i < 8; i++) {
            int w = tt + 128 * i;                    // 1024 words
            bbf[(w >> 5) * 36 + (w & 31)] = src[w];
        }
    }
    __syncthreads();

    // ---- per-warp fragment setup ----
    const int wid = t >> 5;
    const int ln  = t & 31;
    const int g   = ln >> 2;
    const int tig = ln & 3;
    const int row_lo = wid * 16 + g;
    const int row_hi = row_lo + 8;
    const int n_lo = base + row_lo, n_hi = base + row_hi;

    uint32_t afr[4][4];                              // [kstep][reg], resident
#pragma unroll
    for (int ks = 0; ks < 4; ks++) {
        afr[ks][0] = abf[row_lo * 36 + 8 * ks + tig];
        afr[ks][1] = abf[row_hi * 36 + 8 * ks + tig];
        afr[ks][2] = abf[row_lo * 36 + 8 * ks + tig + 4];
        afr[ks][3] = abf[row_hi * 36 + 8 * ks + tig + 4];
    }

    float bv_lo = CUDART_INF_F, bv_hi = CUDART_INF_F;
    int   bi_lo = 0, bi_hi = 0;

    float thr_lo = 0.f, thr_hi = 0.f, exlo = 0.f, exhi = 0.f, eM = 0.f;
    float x2lo = sx2[row_lo], x2hi = sx2[row_hi];
    if (RESCORE) {
        eM   = __uint_as_float(g_emaxr);
        exlo = 0.015625f * sqrtf(x2lo);              // 2 * 2^-7 * ||x||
        exhi = 0.015625f * sqrtf(x2hi);
        thr_lo = __ldg(&g_smin[n_lo]) + exlo * eM + 8e-5f;
        thr_hi = __ldg(&g_smin[n_hi]) + exhi * eM + 8e-5f;
    }

    const uint32_t* ebf32 = (const uint32_t*)g_ebf;

#pragma unroll 1
    for (int c = 0; c < 32; c++) {
        const uint32_t* bcur = bbf + (c & 1) * 1152;
        uint32_t* balt = bbf + ((c + 1) & 1) * 1152;

        // prefetch next B chunk to regs (overlaps mma)
        uint32_t pf[4];
        if (c + 1 < 32) {
#pragma unroll
            for (int i = 0; i < 4; i++)
                pf[i] = __ldg(ebf32 + (c + 1) * 1024 + t + 256 * i);
        }

#pragma unroll
        for (int nf = 0; nf < 4; nf++) {
            float acc[4] = {0.f, 0.f, 0.f, 0.f};
            const uint32_t* bb = bcur + (nf * 8 + g) * 36;
#pragma unroll
            for (int ks = 0; ks < 4; ks++)
                mma_bf16(acc, afr[ks], bb[8 * ks + tig], bb[8 * ks + tig + 4]);

            const int code0 = c * 32 + nf * 8 + tig * 2;   // cols tig*2, +1
            float2 e2p = *(const float2*)&g_e2[code0];
            float s0 = __fmaf_rn(-2.f, acc[0], e2p.x);
            float s1 = __fmaf_rn(-2.f, acc[1], e2p.y);
            float s2 = __fmaf_rn(-2.f, acc[2], e2p.x);
            float s3 = __fmaf_rn(-2.f, acc[3], e2p.y);

            if (!RESCORE) {
                if (s0 < bv_lo) { bv_lo = s0; bi_lo = code0; }
                if (s1 < bv_lo) { bv_lo = s1; bi_lo = code0 + 1; }
                if (s2 < bv_hi) { bv_hi = s2; bi_hi = code0; }
                if (s3 < bv_hi) { bv_hi = s3; bi_hi = code0 + 1; }
            } else {
                float2 sep = *(const float2*)&g_se[code0];
                if (s0 <= thr_lo + exlo * sep.x)
                    rescore(afp + row_lo * ND, x2lo, code0,     emb, &g_best[n_lo]);
                if (s1 <= thr_lo + exlo * sep.y)
                    rescore(afp + row_lo * ND, x2lo, code0 + 1, emb, &g_best[n_lo]);
                if (s2 <= thr_hi + exhi * sep.x)
                    rescore(afp + row_hi * ND, x2hi, code0,     emb, &g_best[n_hi]);
                if (s3 <= thr_hi + exhi * sep.y)
                    rescore(afp + row_hi * ND, x2hi, code0 + 1, emb, &g_best[n_hi]);
            }
        }

        if (c + 1 < 32) {
#pragma unroll
            for (int i = 0; i < 4; i++) {
                int w = t + 256 * i;
                balt[(w >> 5) * 36 + (w & 31)] = pf[i];
            }
        }
        __syncthreads();
    }

    if (!RESCORE) {
        // reduce best across the 4 tig lanes (same point rows); packed u64 min
        unsigned long long p_lo =
            ((unsigned long long)__float_as_uint(bv_lo) << 32) | (unsigned)bi_lo;
        unsigned long long p_hi =
            ((unsigned long long)__float_as_uint(bv_hi) << 32) | (unsigned)bi_hi;
        unsigned long long q;
        q = __shfl_xor_sync(0xffffffffu, p_lo, 1); if (q < p_lo) p_lo = q;
        q = __shfl_xor_sync(0xffffffffu, p_lo, 2); if (q < p_lo) p_lo = q;
        q = __shfl_xor_sync(0xffffffffu, p_hi, 1); if (q < p_hi) p_hi = q;
        q = __shfl_xor_sync(0xffffffffu, p_hi, 2); if (q < p_hi) p_hi = q;
        if (tig == 0) {
            g_smin[n_lo] = __uint_as_float((unsigned)(p_lo >> 32));
            g_smin[n_hi] = __uint_as_float((unsigned)(p_hi >> 32));
        }
    }
}

// ---------------------------------------------------------------------------
// Combine: read g_best -> besti; gather quantized, index, loss partial.
// ---------------------------------------------------------------------------
__global__ void __launch_bounds__(256) vq_combine_kernel(
    const float* __restrict__ x_in,
    const float* __restrict__ emb,
    float* __restrict__ out)
{
    const int t  = threadIdx.x;
    const int n  = blockIdx.x * 256 + t;
    const int b  = n >> 10;
    const int hw = n & 1023;

    const int besti = (int)(g_best[n] & 0xffffffffu);

    const float* xp   = x_in + (size_t)b * (ND * NHW) + hw;
    const float* er   = emb + (size_t)besti * ND;
    float*       qout = out + 1 + (size_t)b * (ND * NHW) + hw;

    double lacc = 0.0;
#pragma unroll
    for (int d = 0; d < ND; d++) {
        float v = er[d];                 // embedding L2-hot gather
        qout[d * NHW] = v;               // coalesced across lanes
        float diff = v - xp[d * NHW];
        lacc += (double)diff * (double)diff;
    }

    out[1 + (size_t)NPTS * ND + n] = (float)besti;   // exact below 2^24

    __shared__ double sd[256];
    sd[t] = lacc;
    __syncthreads();
#pragma unroll
    for (int s = 128; s > 0; s >>= 1) {
        if (t < s) sd[t] += sd[t + s];
        __syncthreads();
    }
    if (t == 0) g_partials[blockIdx.x] = sd[0];
}

// ---------------------------------------------------------------------------
// Final deterministic loss: loss = 1.25 * mean((q - x)^2)
// ---------------------------------------------------------------------------
__global__ void vq_loss_kernel(float* __restrict__ out) {
    __shared__ double sd[128];
    int t = threadIdx.x;
    sd[t] = g_partials[t];
    __syncthreads();
#pragma unroll
    for (int s = 64; s > 0; s >>= 1) {
        if (t < s) sd[t] += sd[t + s];
        __syncthreads();
    }
    if (t == 0) out[0] = (float)(1.25 * sd[0] / (double)((size_t)NPTS * ND));
}

// ---------------------------------------------------------------------------
extern "C" void kernel_launch(void* const* d_in, const int* in_sizes, int n_in,
                              void* d_out, int out_size)
{
    const float* a = (const float*)d_in[0];   // inputs  [32,64,32,32]
    const float* e = (const float*)d_in[1];   // embedding [1024,64]
    if (n_in >= 2 && in_sizes[0] == NK * ND && in_sizes[1] == NPTS * ND) {
        const float* t = a; a = e; e = t;     // defensive order swap
    }
    float* out = (float*)d_out;

    static int attr_set = 0;
    if (!attr_set) {
        cudaFuncSetAttribute(vq_gemm_kernel<1>,
                             cudaFuncAttributeMaxDynamicSharedMemorySize, DYN_B);
        attr_set = 1;
    }

    vq_prep_kernel   <<<32, 256>>>(e);
    vq_gemm_kernel<0><<<256, 256, DYN_A>>>(a, e);
    vq_gemm_kernel<1><<<256, 256, DYN_B>>>(a, e);
    vq_combine_kernel<<<128, 256>>>(a, e, out);
    vq_loss_kernel   <<<1, 128>>>(out);
    (void)out_size;
}

// round 13
// speedup vs baseline: 2.1405x; 2.1405x over previous
#include <cuda_runtime.h>
#include <math_constants.h>

// VectorQuantizer: B=32, D=64, H=W=32, K=1024
// Output layout (f32 concat): [loss(1)][quantized BxDxHxW (2097152)][indices BxHW (32768)]

#define ND 64
#define NHW 1024
#define NK 1024
#define NPTS 32768
#define CHUNK 8
#define CODES_PER_CHUNK (NK / CHUNK)              // 128
#define CODES_PER_ITER 16
#define NITER (CODES_PER_CHUNK / CODES_PER_ITER)  // 8
#define SCAN_THREADS 128
#define SCAN_BLOCKS (CHUNK * NPTS / SCAN_THREADS) // 2048
#define COMB_THREADS 128
#define COMB_BLOCKS (NPTS / COMB_THREADS)         // 256

__device__ float              g_e2[NK];
__device__ unsigned long long g_best[NPTS];       // (dist_bits<<32)|code
__device__ double             g_partials[COMB_BLOCKS];

// ---------------------------------------------------------------------------
// Packed f32x2 helpers (sm_103a FFMA2; ptxas never auto-fuses these)
// ---------------------------------------------------------------------------
__device__ __forceinline__ unsigned long long pack2(float a, float b) {
    unsigned long long r;
    asm("mov.b64 %0, {%1, %2};" : "=l"(r) : "f"(a), "f"(b));
    return r;
}
__device__ __forceinline__ float2 unpack2(unsigned long long v) {
    float2 f;
    asm("mov.b64 {%0, %1}, %2;" : "=f"(f.x), "=f"(f.y) : "l"(v));
    return f;
}
__device__ __forceinline__ unsigned long long fma2(unsigned long long a,
                                                   unsigned long long b,
                                                   unsigned long long c) {
    unsigned long long d;
    asm("fma.rn.f32x2 %0, %1, %2, %3;" : "=l"(d) : "l"(a), "l"(b), "l"(c));
    return d;
}

// ---------------------------------------------------------------------------
// Prep: e2 (proven order) + init g_best to +inf
// ---------------------------------------------------------------------------
__global__ void vq_prep_kernel(const float* __restrict__ emb) {
    int tid = blockIdx.x * 256 + threadIdx.x;   // 8192 threads
    int k   = tid >> 3;
    int sub = tid & 7;
    const float* r = emb + k * ND + sub * 8;
    float s = 0.f;
#pragma unroll
    for (int d = 0; d < 8; d++) s = __fmaf_rn(r[d], r[d], s);
    s += __shfl_down_sync(0xffffffffu, s, 4, 8);
    s += __shfl_down_sync(0xffffffffu, s, 2, 8);
    s += __shfl_down_sync(0xffffffffu, s, 1, 8);
    if (sub == 0) g_e2[k] = s;
#pragma unroll
    for (int i = 0; i < 4; i++)
        g_best[tid + 8192 * i] = 0xFFFFFFFFFFFFFFFFull;
}

// ---------------------------------------------------------------------------
// Scan kernel: 2048 CTAs x 128 threads. blockIdx = point-group(256) x chunk(8).
// Each thread: 1 point, 128 codes (8 tiles of 16). Per-code dot order is
// bit-identical to the proven-passing kernels. Merge via exact u64 atomicMin:
// (dist_bits<<32)|code == reference's strict-< ascending-index argmin
// (dist > 0 so float bits are monotone; min is order-independent).
// ---------------------------------------------------------------------------
__global__ void __launch_bounds__(SCAN_THREADS, 4) vq_scan_kernel(
    const float* __restrict__ x_in,
    const float* __restrict__ emb)
{
    const int t  = threadIdx.x;
    const int c  = blockIdx.x & (CHUNK - 1);      // chunk id 0..7
    const int g  = blockIdx.x >> 3;               // point group 0..255
    const int n  = g * SCAN_THREADS + t;          // point id
    const int b  = n >> 10;
    const int hw = n & 1023;

    const float* xp = x_in + (size_t)b * (ND * NHW) + hw;

    // Load + pack x (coalesced across lanes); x2 in ascending d (as before).
    unsigned long long xq[32];
    float x2 = 0.f;
#pragma unroll
    for (int p = 0; p < 32; p++) {
        float a  = xp[(2 * p) * NHW];
        float cc = xp[(2 * p + 1) * NHW];
        x2 = __fmaf_rn(a, a, x2);
        x2 = __fmaf_rn(cc, cc, x2);
        xq[p] = pack2(a, cc);
    }

    // Tiles: 16 codes * 64 floats = 256 float4 = 4KB, ping-pong
    __shared__ float4 sbuf[2][CODES_PER_ITER * 16];
    const float4* __restrict__ embc =
        (const float4*)emb + (size_t)c * CODES_PER_CHUNK * 16;

    sbuf[0][t]       = embc[t];
    sbuf[0][t + 128] = embc[t + 128];
    __syncthreads();

    float bestv = CUDART_INF_F;
    int   besti = 0;
    const int code_base = c * CODES_PER_CHUNK;

#pragma unroll 1
    for (int i = 0; i < NITER; i++) {
        const int cur = i & 1;
        if (i + 1 < NITER) {
            sbuf[cur ^ 1][t]       = embc[(i + 1) * 256 + t];
            sbuf[cur ^ 1][t + 128] = embc[(i + 1) * 256 + 128 + t];
        }

        const ulonglong2* __restrict__ sp = (const ulonglong2*)sbuf[cur];

        unsigned long long acc[CODES_PER_ITER];
#pragma unroll
        for (int j = 0; j < CODES_PER_ITER; j++) acc[j] = 0ull;

#pragma unroll
        for (int j = 0; j < CODES_PER_ITER; j++) {
#pragma unroll
            for (int p2 = 0; p2 < 16; p2++) {
                ulonglong2 e = sp[j * 16 + p2];            // 16B broadcast LDS
                acc[j] = fma2(xq[2 * p2 + 0], e.x, acc[j]);
                acc[j] = fma2(xq[2 * p2 + 1], e.y, acc[j]);
            }
        }

        const int c0 = code_base + i * CODES_PER_ITER;
#pragma unroll
        for (int j = 0; j < CODES_PER_ITER; j++) {
            float e2v = g_e2[c0 + j];
            float2 a  = unpack2(acc[j]);
            float dot = __fadd_rn(a.x, a.y);
            float dv  = __fadd_rn(__fmaf_rn(-2.0f, dot, x2), e2v);
            if (dv < bestv) { bestv = dv; besti = c0 + j; }   // first-index ties
        }
        __syncthreads();
    }

    // dist > 0 (||x-e||^2 scale ~64) -> float bits monotone; exact merge.
    unsigned long long packed =
        ((unsigned long long)__float_as_uint(bestv) << 32) | (unsigned)besti;
    atomicMin(&g_best[n], packed);
}

// ---------------------------------------------------------------------------
// Combine: read winner, gather quantized row (float4), index, loss partial.
// ---------------------------------------------------------------------------
__global__ void __launch_bounds__(COMB_THREADS) vq_combine_kernel(
    const float* __restrict__ x_in,
    const float* __restrict__ emb,
    float* __restrict__ out)
{
    const int t  = threadIdx.x;
    const int n  = blockIdx.x * COMB_THREADS + t;
    const int b  = n >> 10;
    const int hw = n & 1023;

    const int besti = (int)(g_best[n] & 0xffffffffu);

    const float*  xp   = x_in + (size_t)b * (ND * NHW) + hw;
    const float4* er4  = (const float4*)(emb + (size_t)besti * ND);
    float*        qout = out + 1 + (size_t)b * (ND * NHW) + hw;

    double lacc = 0.0;
#pragma unroll
    for (int p = 0; p < 16; p++) {
        float4 v = __ldg(&er4[p]);               // contiguous row, L2-hot
        float x0 = xp[(4 * p + 0) * NHW];
        float x1 = xp[(4 * p + 1) * NHW];
        float x2v = xp[(4 * p + 2) * NHW];
        float x3 = xp[(4 * p + 3) * NHW];
        qout[(4 * p + 0) * NHW] = v.x;           // coalesced across lanes
        qout[(4 * p + 1) * NHW] = v.y;
        qout[(4 * p + 2) * NHW] = v.z;
        qout[(4 * p + 3) * NHW] = v.w;
        float d0 = v.x - x0, d1 = v.y - x1, d2 = v.z - x2v, d3 = v.w - x3;
        lacc += (double)d0 * d0;                 // ascending-d order preserved
        lacc += (double)d1 * d1;
        lacc += (double)d2 * d2;
        lacc += (double)d3 * d3;
    }

    out[1 + (size_t)NPTS * ND + n] = (float)besti;   // exact below 2^24

    __shared__ double sd[COMB_THREADS];
    sd[t] = lacc;
    __syncthreads();
#pragma unroll
    for (int s = COMB_THREADS / 2; s > 0; s >>= 1) {
        if (t < s) sd[t] += sd[t + s];
        __syncthreads();
    }
    if (t == 0) g_partials[blockIdx.x] = sd[0];
}

// ---------------------------------------------------------------------------
// Final deterministic loss: loss = 1.25 * mean((q - x)^2)
// ---------------------------------------------------------------------------
__global__ void vq_loss_kernel(float* __restrict__ out) {
    __shared__ double sd[COMB_BLOCKS];
    int t = threadIdx.x;
    sd[t] = g_partials[t];
    __syncthreads();
#pragma unroll
    for (int s = COMB_BLOCKS / 2; s > 0; s >>= 1) {
        if (t < s) sd[t] += sd[t + s];
        __syncthreads();
    }
    if (t == 0) out[0] = (float)(1.25 * sd[0] / (double)((size_t)NPTS * ND));
}

// ---------------------------------------------------------------------------
extern "C" void kernel_launch(void* const* d_in, const int* in_sizes, int n_in,
                              void* d_out, int out_size)
{
    const float* a = (const float*)d_in[0];   // inputs  [32,64,32,32]
    const float* e = (const float*)d_in[1];   // embedding [1024,64]
    if (n_in >= 2 && in_sizes[0] == NK * ND && in_sizes[1] == NPTS * ND) {
        const float* t = a; a = e; e = t;     // defensive order swap
    }
    float* out = (float*)d_out;

    vq_prep_kernel   <<<32, 256>>>(e);
    vq_scan_kernel   <<<SCAN_BLOCKS, SCAN_THREADS>>>(a, e);
    vq_combine_kernel<<<COMB_BLOCKS, COMB_THREADS>>>(a, e, out);
    vq_loss_kernel   <<<1, COMB_BLOCKS>>>(out);
    (void)out_size;
}